// round 17
// baseline (speedup 1.0000x reference)
#include <cuda_runtime.h>
#include <cstdint>

// Problem constants
#define BB   8
#define CIN  128
#define HH   128
#define WW   128
#define HWP  (HH*WW)          // 16384
#define COUT 256
#define GG   8

typedef unsigned long long ull;

// Scratch (static device globals — no allocation)
__device__ float  d_P[BB * CIN * 52];          // pooled grids: [b][ch][52]
__device__ float4 d_GI4[BB * GG * 32 * 16];    // (0.5*gi_r, 0.5*gi_z, gi_n, 0)
__device__ float2 d_WpackA[GG * 32 * 16];      // 0.5*(Wcomb_r, Wcomb_z) per group
__device__ float2 d_WpackB[GG * 32 * 16];      // (Wcomb_n, W_center) per group

// ---- packed f32x2 helpers (FFMA2 — only reachable via PTX) ----------------
__device__ __forceinline__ ull pk2(float lo, float hi) {
    ull r;
    asm("mov.b64 %0, {%1,%2};" : "=l"(r) : "f"(lo), "f"(hi));
    return r;
}
__device__ __forceinline__ void upk2(float& lo, float& hi, ull v) {
    asm("mov.b64 {%0,%1}, %2;" : "=f"(lo), "=f"(hi) : "l"(v));
}
__device__ __forceinline__ float lo2(ull v) {
    float a, b;
    asm("mov.b64 {%0,%1}, %2;" : "=f"(a), "=f"(b) : "l"(v));
    return a;
}
__device__ __forceinline__ ull fma2(ull a, ull b, ull c) {
    ull d;
    asm("fma.rn.f32x2 %0, %1, %2, %3;" : "=l"(d) : "l"(a), "l"(b), "l"(c));
    return d;
}
__device__ __forceinline__ ull mul2(ull a, ull b) {
    ull d;
    asm("mul.rn.f32x2 %0, %1, %2;" : "=l"(d) : "l"(a), "l"(b));
    return d;
}
__device__ __forceinline__ ull add2(ull a, ull b) {
    ull d;
    asm("add.rn.f32x2 %0, %1, %2;" : "=l"(d) : "l"(a), "l"(b));
    return d;
}
__device__ __forceinline__ float tanha(float a) {
    float r;
    asm("tanh.approx.f32 %0, %1;" : "=f"(r) : "f"(a));
    return r;
}

// ---------------------------------------------------------------------------
// K1: adaptive average pooling — single-wave, MLP-16 version.
// 512 blocks, each processing TWO channels sequentially (whole grid fits in
// one wave at 4 blocks/SM: 512 <= 592, killing the wave-tail that capped the
// R15 version). 256 threads: half = tid>>7 processes rows [half*64,+64),
// column w = tid&127. Rows consumed in explicit 16-row load buffers (16
// independent LDGs before any accumulation; MLP=16 covers DRAM latency).
// Bins: [0]=full(O=1), [1..11]=O11, [12..14]=O3, [15..19]=O5 (floor-start /
// ceil-end adaptive bins, may overlap one row; membership folds at compile
// time).
// ---------------------------------------------------------------------------
__device__ __host__ __forceinline__ constexpr bool inbin(int h, int i, int O) {
    return (h >= (i * 128) / O) && (h < ((i + 1) * 128 + O - 1) / O);
}

__global__ void __launch_bounds__(256, 4) k_pool(const float* __restrict__ x) {
    __shared__ float Hs[2][20 * 128];
    __shared__ float P11[11 * 4];

    int tid = threadIdx.x;
    int half = tid >> 7;
    int w = tid & 127;

#define POOL_BLOCK(BASE, KK)                                                \
    {                                                                       \
        float buf[16];                                                      \
        _Pragma("unroll")                                                   \
        for (int j = 0; j < 16; ++j)                                        \
            buf[j] = xp[((BASE) + (KK) + j) * 128];                         \
        _Pragma("unroll")                                                   \
        for (int j = 0; j < 16; ++j) {                                      \
            const int h = (BASE) + (KK) + j;                                \
            float v = buf[j];                                               \
            acc[0] += v;                                                    \
            _Pragma("unroll")                                               \
            for (int i = 0; i < 11; ++i) if (inbin(h, i, 11)) acc[1 + i] += v;  \
            _Pragma("unroll")                                               \
            for (int i = 0; i < 3; ++i)  if (inbin(h, i, 3))  acc[12 + i] += v; \
            _Pragma("unroll")                                               \
            for (int i = 0; i < 5; ++i)  if (inbin(h, i, 5))  acc[15 + i] += v; \
        }                                                                   \
    }

#pragma unroll 1
    for (int c = 0; c < 2; ++c) {
        int bc = blockIdx.x * 2 + c;   // b*128+ch
        const float* xp = x + (size_t)bc * HWP + w;

        float acc[20];
#pragma unroll
        for (int i = 0; i < 20; ++i) acc[i] = 0.f;

        if (half == 0) {
            POOL_BLOCK(0, 0)  POOL_BLOCK(0, 16)
            POOL_BLOCK(0, 32) POOL_BLOCK(0, 48)
        } else {
            POOL_BLOCK(64, 0)  POOL_BLOCK(64, 16)
            POOL_BLOCK(64, 32) POOL_BLOCK(64, 48)
        }

#pragma unroll
        for (int bi = 0; bi < 20; ++bi) Hs[half][bi * 128 + w] = acc[bi];
        __syncthreads();

        for (int idx = tid; idx < 20 * 128; idx += 256) Hs[0][idx] += Hs[1][idx];
        __syncthreads();

        int t = tid;
        if (t >= 64 && t < 108) {
            int u = t - 64; int i = u >> 2, q = u & 3;
            const float* Hp = &Hs[0][(1 + i) * 128 + q * 32];
            float s = 0.f;
#pragma unroll
            for (int k = 0; k < 32; ++k) s += Hp[k];
            P11[i * 4 + q] = s;
        }
        __syncthreads();

        if (t < 52) {
            float sum = 0.f;
            float cnt;
            if (t < 11) {                 // br0 (1,11)
                int j = t;
                int s = (j * 128) / 11, e = ((j + 1) * 128 + 10) / 11;
                for (int ww = s; ww < e; ++ww) sum += Hs[0][ww];
                cnt = 128.f * (float)(e - s);
            } else if (t < 22) {          // br1 (11,1)
                int i = t - 11;
                int sH = (i * 128) / 11, eH = ((i + 1) * 128 + 10) / 11;
                sum = (P11[i * 4] + P11[i * 4 + 1]) + (P11[i * 4 + 2] + P11[i * 4 + 3]);
                cnt = (float)(eH - sH) * 128.f;
            } else if (t < 37) {          // br2 (3,5)
                int u = t - 22; int i = u / 5, j = u % 5;
                int sH = (i * 128) / 3, eH = ((i + 1) * 128 + 2) / 3;
                int s = (j * 128) / 5, e = ((j + 1) * 128 + 4) / 5;
                const float* Hp = &Hs[0][(12 + i) * 128];
                for (int ww = s; ww < e; ++ww) sum += Hp[ww];
                cnt = (float)(eH - sH) * (float)(e - s);
            } else {                      // br3 (5,3)
                int u = t - 37; int i = u / 3, j = u % 3;
                int sH = (i * 128) / 5, eH = ((i + 1) * 128 + 4) / 5;
                int s = (j * 128) / 3, e = ((j + 1) * 128 + 2) / 3;
                const float* Hp = &Hs[0][(15 + i) * 128];
                for (int ww = s; ww < e; ++ww) sum += Hp[ww];
                cnt = (float)(eH - sH) * (float)(e - s);
            }
            d_P[bc * 52 + t] = sum / cnt;
        }
        __syncthreads();   // Hs reused by next channel
    }
#undef POOL_BLOCK
}

// ---------------------------------------------------------------------------
// K2 (fused k_q + k_gi + k_wcomb). r/z outputs pre-scaled by 0.5 so the
// sigmoid's half-argument falls out of the main kernel's accumulator.
// ---------------------------------------------------------------------------
__global__ void k_qgi(const float* __restrict__ Wm,
                      const float* __restrict__ W0, const float* __restrict__ b0,
                      const float* __restrict__ W1, const float* __restrict__ b1,
                      const float* __restrict__ W2, const float* __restrict__ b2,
                      const float* __restrict__ W3, const float* __restrict__ b3,
                      const float* __restrict__ Wih, const float* __restrict__ bih,
                      const float* __restrict__ Whh, const float* __restrict__ Wc) {
    __shared__ float ssh[32 * 16];
    int t = threadIdx.x;               // 512 threads

    if (blockIdx.x >= 64) {
        int g = blockIdx.x - 64;
        ssh[t] = Wc[g * 512 + t];
        __syncthreads();

        int o = t >> 4, i = t & 15;
        const float* Wr = &Whh[(size_t)(g * 96 + o) * 32];
        const float* Wz = Wr + 32 * 32;
        const float* Wn = Wz + 32 * 32;
        float ar = 0.f, az = 0.f, an = 0.f;
#pragma unroll
        for (int h = 0; h < 32; ++h) {
            float c = ssh[h * 16 + i];
            ar += Wr[h] * c;
            az += Wz[h] * c;
            an += Wn[h] * c;
        }
        d_WpackA[(size_t)g * 512 + t] = make_float2(0.5f * ar, 0.5f * az);
        d_WpackB[(size_t)g * 512 + t] = make_float2(an, ssh[t]);
        return;
    }

    int bg = blockIdx.x;               // 0..63
    int b = bg >> 3, g = bg & 7;
    int br = g >> 1;
    const float* Wl; const float* bl; int cdim, base;
    if (br == 0)      { Wl = W0; bl = b0; cdim = 11; base = 0;  }
    else if (br == 1) { Wl = W1; bl = b1; cdim = 11; base = 11; }
    else if (br == 2) { Wl = W2; bl = b2; cdim = 15; base = 22; }
    else              { Wl = W3; bl = b3; cdim = 15; base = 37; }

    int ml = t >> 4, u = t & 15;
    float outq = 0.f;
    if (u < cdim) {
        int gl = ml >> 1, o = ml & 1;
        int gm = 16 * g + gl;
#pragma unroll
        for (int j = 0; j < 4; ++j) {
            int ch = 64 * (g & 1) + 4 * gl + j;
            const float* Pp = &d_P[(b * 128 + ch) * 52 + base];
            float q = bl[u];
            for (int v = 0; v < cdim; ++v) q += Wl[u * cdim + v] * Pp[v];
            outq += Wm[gm * 8 + o * 4 + j] * q;
        }
    }
    ssh[t] = outq;
    __syncthreads();

    int o = t >> 4;                    // 0..31
    float ar = bih[g * 96 + o];
    float az = bih[g * 96 + 32 + o];
    float an = bih[g * 96 + 64 + o];
    const float* Wr = &Wih[(size_t)(g * 96 + o) * 32];
    const float* Wz = Wr + 32 * 32;
    const float* Wn = Wz + 32 * 32;
#pragma unroll
    for (int ml2 = 0; ml2 < 32; ++ml2) {
        float q = ssh[ml2 * 16 + u];
        ar += Wr[ml2] * q;
        az += Wz[ml2] * q;
        an += Wn[ml2] * q;
    }
    d_GI4[(size_t)bg * 512 + t] = make_float4(0.5f * ar, 0.5f * az, an, 0.f);
}

// ---------------------------------------------------------------------------
// K3: main fused kernel (R13 best-known) — gate-packed f32x2 weights,
// 2 adjacent pixels per thread, per-row h-pre-interp GI grids, 2-tap w-lerp
// folded into gate accumulators; n-grid lerped packed; sigmoid half-scale
// pre-folded into weights.
// ---------------------------------------------------------------------------
__global__ void __launch_bounds__(256, 2) k_main(const float* __restrict__ x,
                                                 const float* __restrict__ bhh,
                                                 float* __restrict__ out) {
    __shared__ __align__(16) ull sWA[512];
    __shared__ __align__(16) ull sWB[512];
    __shared__ __align__(16) ulonglong2 sGrow[4 * 32 * 16];   // 32KB
    __shared__ ull sbA[32];
    __shared__ ull sbB[32];

    int tid = threadIdx.x;
    int tile = blockIdx.x & 31;          // 32 tiles of 512 pixels (4 rows each)
    int g    = (blockIdx.x >> 5) & 7;
    int b    = blockIdx.x >> 8;

    // branch params (uniform per block)
    int br = g >> 1;
    int nH = (br == 0) ? 1 : (br == 1) ? 11 : (br == 2) ? 3 : 5;
    int nW = (br == 0) ? 11 : (br == 1) ? 1 : (br == 2) ? 5 : 3;
    int ci = (br == 1) ? 1 : (br == 2) ? 5 : (br == 3) ? 3 : 0;

    {
        const ull* wa = (const ull*)(d_WpackA + (size_t)g * 512);
        const ull* wb = (const ull*)(d_WpackB + (size_t)g * 512);
        for (int i = tid; i < 512; i += 256) {
            sWA[i] = wa[i];
            sWB[i] = wb[i];
        }
        if (tid < 32) {
            float br_ = bhh[g * 96 + tid];
            float bz_ = bhh[g * 96 + 32 + tid];
            float bn_ = bhh[g * 96 + 64 + tid];
            sbA[tid] = pk2(0.5f * br_, 0.5f * bz_);
            sbB[tid] = pk2(bn_, 0.f);
        }
        // h-pre-interpolated GI grid: 4 rows x 32 o x 16 j
        const float4* gsrc = d_GI4 + (size_t)(b * 8 + g) * 512;
#pragma unroll
        for (int pass = 0; pass < 8; ++pass) {
            int idx = pass * 256 + tid;          // 0..2047
            int row = idx >> 9;                  // 0..3
            int oo  = (idx >> 4) & 31;
            int j   = idx & 15;
            int jj  = (j < nW) ? j : (nW - 1);   // clamp padded slots in-bounds
            int hg  = tile * 4 + row;
            float fh = 0.f; int i0 = 0, i1 = 0;
            if (nH > 1) {
                float s = (float)(hg * (nH - 1)) * (1.f / 127.f);
                i0 = (int)s; if (i0 > nH - 2) i0 = nH - 2;
                fh = s - (float)i0;
                i1 = i0 + 1;
            }
            float4 t0 = gsrc[oo * 16 + i0 * ci + jj];
            float4 t1 = gsrc[oo * 16 + i1 * ci + jj];
            float omfh = 1.f - fh;
            float4 r;
            r.x = omfh * t0.x + fh * t1.x;
            r.y = omfh * t0.y + fh * t1.y;
            r.z = omfh * t0.z + fh * t1.z;
            r.w = 0.f;
            ((float4*)sGrow)[idx] = r;
        }
    }
    __syncthreads();

    int p0 = tile * 512 + tid * 2;       // pixel 0; pixel 1 = p0 + 1 (same row)
    int w0 = p0 & 127, w1 = w0 + 1;
    int rowInBlk = tid >> 6;             // warp-uniform (each warp = one row)

    // load x for both pixels (LDG.64), duplicated into packed lanes
    ull xv0[16], xv1[16];
    const float* xb = x + ((size_t)(b * 128 + g * 16)) * HWP + p0;
#pragma unroll
    for (int i = 0; i < 16; ++i) {
        float2 v = *(const float2*)(xb + (size_t)i * HWP);
        xv0[i] = pk2(v.x, v.x);
        xv1[i] = pk2(v.y, v.y);
    }

    // w-interp setup per pixel
    float fw0 = 0.f; int j00 = 0;
    float fw1 = 0.f; int j01 = 0;
    if (nW > 1) {
        float s0 = (float)(w0 * (nW - 1)) * (1.f / 127.f);
        j00 = (int)s0; if (j00 > nW - 2) j00 = nW - 2;
        fw0 = s0 - (float)j00;
        float s1 = (float)(w1 * (nW - 1)) * (1.f / 127.f);
        j01 = (int)s1; if (j01 > nW - 2) j01 = nW - 2;
        fw1 = s1 - (float)j01;
    }
    float om0 = 1.f - fw0, om1 = 1.f - fw1;
    ull fw0d = pk2(fw0, fw0), om0d = pk2(om0, om0);
    ull fw1d = pk2(fw1, fw1), om1d = pk2(om1, om1);

    const ulonglong2* growRow = sGrow + rowInBlk * 512;   // [o][j]
    float* ob = out + ((size_t)(b * 256 + g)) * HWP + p0;

#pragma unroll 4
    for (int o = 0; o < 32; ++o) {
        ull bA = sbA[o];
        ull bB = sbB[o];
        ull accA0 = bA, accB0 = bB;
        ull accA1 = bA, accB1 = bB;
        const ulonglong2* A2 = (const ulonglong2*)(sWA + o * 16);
        const ulonglong2* B2 = (const ulonglong2*)(sWB + o * 16);
#pragma unroll
        for (int k = 0; k < 8; ++k) {
            ulonglong2 wa = A2[k];
            ulonglong2 wb = B2[k];
            accA0 = fma2(wa.x, xv0[2 * k],     accA0);
            accA0 = fma2(wa.y, xv0[2 * k + 1], accA0);
            accB0 = fma2(wb.x, xv0[2 * k],     accB0);
            accB0 = fma2(wb.y, xv0[2 * k + 1], accB0);
            accA1 = fma2(wa.x, xv1[2 * k],     accA1);
            accA1 = fma2(wa.y, xv1[2 * k + 1], accA1);
            accB1 = fma2(wb.x, xv1[2 * k],     accB1);
            accB1 = fma2(wb.y, xv1[2 * k + 1], accB1);
        }

        const ulonglong2* gro = growRow + o * 16;
        float y0, y1;

        // ---- pixel 0: 2-tap w-lerp, (r,z) folded into acc, n lerp packed ----
        {
            ulonglong2 t0 = gro[j00], t1 = gro[j00 + 1];
            ull acc = fma2(om0d, t0.x, fma2(fw0d, t1.x, accA0));  // 0.5*(i+h)
            ull innp = fma2(om0d, t0.y, mul2(fw0d, t1.y));
            float vr, vz;
            upk2(vr, vz, acc);
            float hn, cg;
            upk2(hn, cg, accB0);
            float inn = lo2(innp);

            float r = fmaf(0.5f, tanha(vr), 0.5f);
            float z = fmaf(0.5f, tanha(vz), 0.5f);
            float nt = tanha(fmaf(r, hn, inn));
            y0 = fmaf(z, cg - nt, nt);
        }
        // ---- pixel 1 ----
        {
            ulonglong2 t0 = gro[j01], t1 = gro[j01 + 1];
            ull acc = fma2(om1d, t0.x, fma2(fw1d, t1.x, accA1));
            ull innp = fma2(om1d, t0.y, mul2(fw1d, t1.y));
            float vr, vz;
            upk2(vr, vz, acc);
            float hn, cg;
            upk2(hn, cg, accB1);
            float inn = lo2(innp);

            float r = fmaf(0.5f, tanha(vr), 0.5f);
            float z = fmaf(0.5f, tanha(vz), 0.5f);
            float nt = tanha(fmaf(r, hn, inn));
            y1 = fmaf(z, cg - nt, nt);
        }

        *(float2*)(ob + (size_t)(o * 8) * HWP) = make_float2(y0, y1);
    }
}

// ---------------------------------------------------------------------------
extern "C" void kernel_launch(void* const* d_in, const int* in_sizes, int n_in,
                              void* d_out, int out_size) {
    (void)in_sizes; (void)n_in; (void)out_size;
    const float* x   = (const float*)d_in[0];
    const float* Wc  = (const float*)d_in[1];
    const float* W0  = (const float*)d_in[2];
    const float* b0  = (const float*)d_in[3];
    const float* W1  = (const float*)d_in[4];
    const float* b1  = (const float*)d_in[5];
    const float* W2  = (const float*)d_in[6];
    const float* b2  = (const float*)d_in[7];
    const float* W3  = (const float*)d_in[8];
    const float* b3  = (const float*)d_in[9];
    const float* Wm  = (const float*)d_in[10];
    const float* Wih = (const float*)d_in[11];
    const float* Whh = (const float*)d_in[12];
    const float* bih = (const float*)d_in[13];
    const float* bhh = (const float*)d_in[14];
    float* out = (float*)d_out;

    k_pool<<<BB * CIN / 2, 256>>>(x);
    k_qgi<<<BB * GG + GG, 512>>>(Wm, W0, b0, W1, b1, W2, b2, W3, b3, Wih, bih, Whh, Wc);
    k_main<<<BB * GG * (HWP / 512), 256>>>(x, bhh, out);
}